// round 15
// baseline (speedup 1.0000x reference)
#include <cuda_runtime.h>
#include <math.h>

#define HD     128
#define HEADS  4
#define CDIM   32
#define NLAYER 4
#define NEG    100
#define HS     128

#define N_MAX  2048
#define E_MAX  4096
#define B_MAX  32
#define BE_MAX (B_MAX * NEG)

// ---------------- scratch (device globals; no allocation allowed) ----------
__device__ float g_h   [N_MAX * HD];
__device__ float g_e   [E_MAX * HD];
__device__ float g_xl  [N_MAX * HD];
__device__ float g_ssrc[N_MAX * HEADS];
__device__ float g_sdst[N_MAX * HEADS];
__device__ float g_ae2 [NLAYER * E_MAX * HEADS];   // all layers' edge attention
__device__ float g_aesum2[NLAYER * HEADS];
__device__ float g_den  [N_MAX * HEADS];
__device__ float g_agg  [N_MAX * HD];
__device__ float g_onsite[N_MAX];
__device__ float g_coup  [E_MAX];
__device__ int   g_dna  [N_MAX];
__device__ int   g_loc  [N_MAX];
// NEGF scratch
__device__ float g_hbd[B_MAX * HS];
__device__ float g_hb1[B_MAX * HS];
__device__ float g_hb2[B_MAX * HS];
__device__ float g_dvb[B_MAX * HS];
__device__ float2 g_lu[BE_MAX * 5 * HS];
__device__ float g_Tacc[BE_MAX];
__device__ float g_Dacc[BE_MAX];
__device__ int   g_cnt [BE_MAX];

// complex mul / fms helpers
#define CMUL(o, a, b) do { \
    (o).x = (a).x * (b).x - (a).y * (b).y; \
    (o).y = (a).x * (b).y + (a).y * (b).x; \
} while (0)
#define CFMS(m, c, r) do { \
    (m).x = fmaf(-(c).x, (r).x, fmaf((c).y, (r).y, (m).x)); \
    (m).y = fmaf(-(c).x, (r).y, fmaf(-(c).y, (r).x, (m).y)); \
} while (0)

// ---------------- GNN kernels ----------------------------------------------
__global__ void k_init_h(const float* __restrict__ x, const float* __restrict__ w,
                         const float* __restrict__ b) {
    int n = blockIdx.x, t = threadIdx.x;
    float acc = b[t];
#pragma unroll
    for (int k = 0; k < 4; k++) acc = fmaf(x[n * 4 + k], w[k * HD + t], acc);
    g_h[n * HD + t] = acc;
    g_agg[n * HD + t] = 0.f;
    if (t < HEADS) g_den[n * HEADS + t] = 0.f;
    if (n == 0 && t < NLAYER * HEADS) g_aesum2[t] = 0.f;
}

__global__ void k_init_e(const float* __restrict__ ea, const float* __restrict__ w,
                         const float* __restrict__ b) {
    int n = blockIdx.x, t = threadIdx.x;
    float acc = b[t];
#pragma unroll
    for (int k = 0; k < 5; k++) acc = fmaf(ea[n * 5 + k], w[k * HD + t], acc);
    g_e[n * HD + t] = acc;
}

// ALL layers' edge attention projections upfront (g_e fixed after k_init_e).
// grid = NLAYER * nb_e; 4 edges per block.
__global__ void k_eproj(const float* __restrict__ gat_le,
                        const float* __restrict__ att_ed, int E, int nb_e) {
    __shared__ float rows[4][HD];
    __shared__ float outs[4][HD];
    int t = threadIdx.x;
    int l = blockIdx.x / nb_e;
    int e0 = (blockIdx.x % nb_e) * 4;
    int cnt = E - e0; if (cnt > 4) cnt = 4;
    const float* We = gat_le + l * HD * HD;
    const float* aedge = att_ed + l * HEADS * CDIM;
#pragma unroll
    for (int rr = 0; rr < 4; rr++)
        rows[rr][t] = (rr < cnt) ? g_e[(size_t)(e0 + rr) * HD + t] : 0.f;
    __syncthreads();
    float a0 = 0.f, a1 = 0.f, a2 = 0.f, a3 = 0.f;
#pragma unroll 4
    for (int k = 0; k < HD; k++) {
        float wv = We[k * HD + t];
        a0 = fmaf(rows[0][k], wv, a0);
        a1 = fmaf(rows[1][k], wv, a1);
        a2 = fmaf(rows[2][k], wv, a2);
        a3 = fmaf(rows[3][k], wv, a3);
    }
    outs[0][t] = a0; outs[1][t] = a1; outs[2][t] = a2; outs[3][t] = a3;
    __syncthreads();
    int w = t >> 5, lane = t & 31;
    if (w < cnt) {
#pragma unroll
        for (int h = 0; h < HEADS; h++) {
            float v = outs[w][h * 32 + lane] * aedge[h * 32 + lane];
#pragma unroll
            for (int o = 16; o > 0; o >>= 1)
                v += __shfl_down_sync(0xffffffffu, v, o);
            if (lane == 0) {
                g_ae2[(size_t)l * E_MAX * HEADS + (e0 + w) * HEADS + h] = v;
                atomicAdd(&g_aesum2[l * HEADS + h], v);
            }
        }
    }
}

// node projection + attention dot products: 4 nodes per block
__global__ void k_attn(const float* __restrict__ Wn, const float* __restrict__ asrc,
                       const float* __restrict__ adst, int N) {
    __shared__ float rows[4][HD];
    __shared__ float outs[4][HD];
    int t = threadIdx.x;
    int r0 = blockIdx.x * 4;
    int cnt = N - r0; if (cnt > 4) cnt = 4;
#pragma unroll
    for (int rr = 0; rr < 4; rr++)
        rows[rr][t] = (rr < cnt) ? g_h[(size_t)(r0 + rr) * HD + t] : 0.f;
    __syncthreads();
    float a0 = 0.f, a1 = 0.f, a2 = 0.f, a3 = 0.f;
#pragma unroll 4
    for (int k = 0; k < HD; k++) {
        float wv = Wn[k * HD + t];
        a0 = fmaf(rows[0][k], wv, a0);
        a1 = fmaf(rows[1][k], wv, a1);
        a2 = fmaf(rows[2][k], wv, a2);
        a3 = fmaf(rows[3][k], wv, a3);
    }
    outs[0][t] = a0; outs[1][t] = a1; outs[2][t] = a2; outs[3][t] = a3;
    if (0 < cnt) g_xl[(size_t)(r0 + 0) * HD + t] = a0;
    if (1 < cnt) g_xl[(size_t)(r0 + 1) * HD + t] = a1;
    if (2 < cnt) g_xl[(size_t)(r0 + 2) * HD + t] = a2;
    if (3 < cnt) g_xl[(size_t)(r0 + 3) * HD + t] = a3;
    __syncthreads();
    int w = t >> 5, lane = t & 31;
    if (w < cnt) {
#pragma unroll
        for (int h = 0; h < HEADS; h++) {
            float xv = outs[w][h * 32 + lane];
            float vs = xv * asrc[h * 32 + lane];
            float vd = xv * adst[h * 32 + lane];
#pragma unroll
            for (int o = 16; o > 0; o >>= 1) {
                vs += __shfl_down_sync(0xffffffffu, vs, o);
                vd += __shfl_down_sync(0xffffffffu, vd, o);
            }
            if (lane == 0) {
                g_ssrc[(r0 + w) * HEADS + h] = vs;
                g_sdst[(r0 + w) * HEADS + h] = vd;
            }
        }
    }
}

// fused attention-weight + aggregation (softmax shift cancels exactly).
// Layer offset into g_ae2/g_aesum2 computed DEVICE-side (device symbols are
// not addressable from host code; on GB300/ATS a host-shadow pointer is
// silently readable and returns stale zeros -- the round-12/14 bug).
__global__ void k_edgeagg(const int* __restrict__ src, const int* __restrict__ dst,
                          int l, int N, int E) {
    int f = blockIdx.x, t = threadIdx.x;
    int hh = t >> 5, lane = t & 31;
    const float* ae_l = g_ae2 + (size_t)l * E_MAX * HEADS;
    int s, d; float ae;
    if (f < E) { s = src[f]; d = dst[f]; ae = ae_l[f * HEADS + hh]; }
    else       { s = f - E; d = s;       ae = g_aesum2[l * HEADS + hh] / (float)E; }
    float a = g_ssrc[s * HEADS + hh] + g_sdst[d * HEADS + hh] + ae;
    a = a > 0.f ? a : 0.2f * a;
    float ex = expf(a);
    atomicAdd(&g_agg[d * HD + t], g_xl[(size_t)s * HD + t] * ex);
    if (lane == 0) atomicAdd(&g_den[d * HEADS + hh], ex);
}

// layernorm(relu(agg/den + bias) + h); zero accumulators for the next layer
__global__ void k_ln(const float* __restrict__ bias, const float* __restrict__ s,
                     const float* __restrict__ bb) {
    __shared__ float red[HD];
    int n = blockIdx.x, t = threadIdx.x;
    float den = g_den[n * HEADS + (t >> 5)];
    float v = g_agg[n * HD + t] / den + bias[t];
    g_agg[n * HD + t] = 0.f;
    __syncthreads();                       // all den reads done before zeroing
    if (t < HEADS) g_den[n * HEADS + t] = 0.f;
    v = v > 0.f ? v : 0.f;
    v += g_h[n * HD + t];
    red[t] = v; __syncthreads();
#pragma unroll
    for (int o = 64; o > 0; o >>= 1) { if (t < o) red[t] += red[t + o]; __syncthreads(); }
    float mu = red[0] / (float)HD;
    __syncthreads();
    float dd = v - mu;
    red[t] = dd * dd; __syncthreads();
#pragma unroll
    for (int o = 64; o > 0; o >>= 1) { if (t < o) red[t] += red[t + o]; __syncthreads(); }
    float var = red[0] / (float)HD;
    g_h[n * HD + t] = dd * rsqrtf(var + 1e-5f) * s[t] + bb[t];
}

// onsite (nodes) + coupling (edges) MLPs: 128 -> 64 (relu) -> 1
__global__ void k_mlp(const float* __restrict__ w1, const float* __restrict__ b1,
                      const float* __restrict__ w2, const float* __restrict__ b2,
                      const float* __restrict__ cw1, const float* __restrict__ cb1,
                      const float* __restrict__ cw2, const float* __restrict__ cb2,
                      int N) {
    __shared__ float in[HD];
    __shared__ float red[64];
    int blk = blockIdx.x, t = threadIdx.x;
    const float *row, *W1, *B1, *W2, *B2;
    if (blk < N) { row = &g_h[(size_t)blk * HD];       W1 = w1;  B1 = b1;  W2 = w2;  B2 = b2;  }
    else         { row = &g_e[(size_t)(blk - N) * HD]; W1 = cw1; B1 = cb1; W2 = cw2; B2 = cb2; }
    in[t] = row[t]; in[t + 64] = row[t + 64];
    __syncthreads();
    float acc = B1[t];
#pragma unroll 8
    for (int k = 0; k < HD; k++) acc = fmaf(in[k], W1[k * 64 + t], acc);
    acc = acc > 0.f ? acc : 0.f;
    red[t] = acc * W2[t];
    __syncthreads();
#pragma unroll
    for (int o = 32; o > 0; o >>= 1) { if (t < o) red[t] += red[t + o]; __syncthreads(); }
    if (t == 0) {
        float o = red[0] + B2[0];
        if (blk < N) g_onsite[blk] = o; else g_coup[blk - N] = o;
    }
}

// dna mask + local index: warp-per-graph ballot scan; zero band arrays
__global__ void k_dna(const float* __restrict__ x, int N, int B) {
    int t = threadIdx.x;
    for (int i = t; i < B * HS; i += blockDim.x) {
        g_hbd[i] = 0.f; g_hb1[i] = 0.f; g_hb2[i] = 0.f;
    }
    int warp = t >> 5, lane = t & 31;
    int npg = N / B;
    if (warp < B) {
        int base = warp * npg;
        int off = 0;
        for (int c = 0; c < npg; c += 32) {
            int li = c + lane;
            int mi = 0;
            if (li < npg) {
                int n = base + li;
                float a = x[n * 4], b = x[n * 4 + 1], cc = x[n * 4 + 2], d = x[n * 4 + 3];
                mi = (a != 0.f || b != 0.f || cc != 0.f || d != 0.f) ? 1 : 0;
                g_dna[n] = mi;
            }
            unsigned bits = __ballot_sync(0xffffffffu, mi);
            if (li < npg) g_loc[base + li] = off + __popc(bits & ((1u << lane) - 1u));
            off += __popc(bits);
        }
    }
}

// assemble bands: onsite->diag, coup->band1/band2, dvb from GL/GR
__global__ void k_basm(const int* __restrict__ src, const int* __restrict__ dst,
                       const int* __restrict__ batch,
                       const float* __restrict__ GL, const float* __restrict__ GR,
                       int N, int E, int B) {
    int idx = blockIdx.x * blockDim.x + threadIdx.x;
    if (idx < N) {
        if (g_dna[idx])
            atomicAdd(&g_hbd[batch[idx] * HS + g_loc[idx]], g_onsite[idx]);
    } else if (idx < N + E) {
        int e = idx - N;
        int s = src[e], d = dst[e];
        if (g_dna[s] && g_dna[d]) {
            int b = batch[s], u = g_loc[s], v = g_loc[d];
            int lo = u < v ? u : v;
            int bd = u < v ? v - u : u - v;
            float cv = g_coup[e];
            if (bd == 1)      atomicAdd(&g_hb1[b * HS + lo], cv);
            else if (bd == 2) atomicAdd(&g_hb2[b * HS + lo], cv);
        }
    } else if (idx < N + E + B * HS) {
        int i = idx - N - E;
        g_dvb[i] = 0.5f * (GL[i] + GR[i]) + 1e-12f;
    }
}

// write dense H (output) from bands
__global__ void k_hwrite(float* __restrict__ H, int B) {
    int idx = blockIdx.x * blockDim.x + threadIdx.x;
    if (idx >= B * HS * HS) return;
    int b = idx / (HS * HS);
    int r = (idx % (HS * HS)) / HS, c = idx % HS;
    float v;
    int lo = r < c ? r : c;
    int bd = r < c ? c - r : r - c;
    if (bd == 0)      v = g_hbd[b * HS + r] + 1e-6f;
    else if (bd == 1) v = g_hb1[b * HS + lo];
    else if (bd == 2) v = g_hb2[b * HS + lo];
    else              v = 0.f;
    H[idx] = v;
}

// ---------------- NEGF: banded (pentadiagonal) solver ----------------------
__global__ void k_lu(int BE) {
    int be = blockIdx.x * blockDim.x + threadIdx.x;
    if (be >= BE) return;
    int b = be / NEG, e = be % NEG;
    float Eg = (float)(-3.0 + 6.0 * (double)e / 99.0);
    const float* hd = g_hbd + b * HS;
    const float* h1 = g_hb1 + b * HS;
    const float* h2 = g_hb2 + b * HS;
    const float* dv = g_dvb + b * HS;
    float2* out = g_lu + (size_t)be * 5 * HS;
    g_Tacc[be] = 0.f; g_Dacc[be] = 0.f; g_cnt[be] = 0;

    float2 e1 = {0.f, 0.f}, e2 = {0.f, 0.f};
    float2 f1 = {0.f, 0.f}, f2 = {0.f, 0.f};
    float2 di1 = {0.f, 0.f}, di2 = {0.f, 0.f};
    for (int i = 0; i < HS; i++) {
        float2 Mi = make_float2(Eg - (hd[i] + 1e-6f), dv[i]);
        float m1 = (i >= 1) ? -h1[i - 1] : 0.f;
        float m2 = (i >= 2) ? -h2[i - 2] : 0.f;
        float2 bi = make_float2(m2 * di2.x, m2 * di2.y);
        float2 tt = make_float2(m1, 0.f);
        CFMS(tt, bi, e2);
        float2 ai; CMUL(ai, tt, di1);
        float2 d = Mi;
        CFMS(d, bi, f2);
        CFMS(d, ai, e1);
        float2 ei = make_float2(0.f, 0.f);
        if (i < HS - 1) { ei = make_float2(-h1[i], 0.f); CFMS(ei, ai, f1); }
        float2 fi = make_float2((i < HS - 2) ? -h2[i] : 0.f, 0.f);
        float inv = 1.f / fmaf(d.x, d.x, d.y * d.y);
        float2 dinv = make_float2(d.x * inv, -d.y * inv);
        out[0 * HS + i] = ai;
        out[1 * HS + i] = bi;
        out[2 * HS + i] = ei;
        out[3 * HS + i] = fi;
        out[4 * HS + i] = dinv;
        e2 = e1; e1 = ei; f2 = f1; f1 = fi; di2 = di1; di1 = dinv;
    }
}

// column solves: one warp-CTA per (b,e, quarter); lane = column j.
__global__ void __launch_bounds__(32) k_solve(
    const float* __restrict__ GL, const float* __restrict__ GR,
    float* __restrict__ Tout, float* __restrict__ Dout, int BE) {
    __shared__ float2 ys[HS * 32];
    __shared__ float2 sa[HS], sb[HS], se[HS], sf[HS], sdi[HS];
    __shared__ float  sgl[HS], sgr[HS];
    int blk = blockIdx.x;
    int be = blk >> 2, q = blk & 3;
    int b = be / NEG;
    int lane = threadIdx.x;
    const float2* lu = g_lu + (size_t)be * 5 * HS;
#pragma unroll
    for (int k = 0; k < 4; k++) {
        int i = lane + k * 32;
        sa[i]  = lu[0 * HS + i];
        sb[i]  = lu[1 * HS + i];
        se[i]  = lu[2 * HS + i];
        sf[i]  = lu[3 * HS + i];
        sdi[i] = lu[4 * HS + i];
        sgl[i] = GL[b * HS + i];
        sgr[i] = GR[b * HS + i];
    }
    __syncwarp();

    int j = q * 32 + lane;
    int i0 = q * 32;
    float2 y1 = {0.f, 0.f}, y2 = {0.f, 0.f};
    for (int i = i0; i < HS; i++) {
        float2 y = make_float2((i == j) ? 1.f : 0.f, 0.f);
        CFMS(y, sa[i], y1);
        CFMS(y, sb[i], y2);
        ys[i * 32 + lane] = y;
        y2 = y1; y1 = y;
    }
    float2 x1 = {0.f, 0.f}, x2 = {0.f, 0.f};
    float tp = 0.f, dj = 0.f;
    for (int i = HS - 1; i >= 0; i--) {
        float2 t = (i >= i0) ? ys[i * 32 + lane] : make_float2(0.f, 0.f);
        CFMS(t, se[i], x1);
        CFMS(t, sf[i], x2);
        float2 x; CMUL(x, t, sdi[i]);
        tp = fmaf(sgl[i], fmaf(x.x, x.x, x.y * x.y), tp);
        if (i == j) dj = x.y;
        x2 = x1; x1 = x;
    }
    tp *= sgr[j];
#pragma unroll
    for (int o = 16; o > 0; o >>= 1) {
        tp += __shfl_down_sync(0xffffffffu, tp, o);
        dj += __shfl_down_sync(0xffffffffu, dj, o);
    }
    if (lane == 0) {
        atomicAdd(&g_Tacc[be], tp);
        atomicAdd(&g_Dacc[be], dj);
        __threadfence();
        int old = atomicAdd(&g_cnt[be], 1);
        if (old == 3) {
            __threadfence();
            Tout[be] = log10f(fmaxf(g_Tacc[be], 1e-16f));
            Dout[be] = log10f(fmaxf(-g_Dacc[be] / 3.14159265358979323846f, 1e-16f));
        }
    }
}

// ---------------- launch ----------------------------------------------------
extern "C" void kernel_launch(void* const* d_in, const int* in_sizes, int n_in,
                              void* d_out, int out_size) {
    const float* x      = (const float*)d_in[0];
    const int*   ei     = (const int*)  d_in[1];
    const float* ea     = (const float*)d_in[2];
    const int*   batch  = (const int*)  d_in[3];
    const float* GL     = (const float*)d_in[4];
    const float* GR     = (const float*)d_in[5];
    const float* node_w = (const float*)d_in[6];
    const float* node_b = (const float*)d_in[7];
    const float* edgep_w= (const float*)d_in[8];
    const float* edgep_b= (const float*)d_in[9];
    const float* gat_lin= (const float*)d_in[10];
    const float* att_src= (const float*)d_in[11];
    const float* att_dst= (const float*)d_in[12];
    const float* gat_le = (const float*)d_in[13];
    const float* att_ed = (const float*)d_in[14];
    const float* gat_b  = (const float*)d_in[15];
    const float* ln_s   = (const float*)d_in[16];
    const float* ln_b   = (const float*)d_in[17];
    const float* on_w1  = (const float*)d_in[18];
    const float* on_b1  = (const float*)d_in[19];
    const float* on_w2  = (const float*)d_in[20];
    const float* on_b2  = (const float*)d_in[21];
    const float* cp_w1  = (const float*)d_in[22];
    const float* cp_b1  = (const float*)d_in[23];
    const float* cp_w2  = (const float*)d_in[24];
    const float* cp_b2  = (const float*)d_in[25];

    int N = in_sizes[0] / 4;
    int E = in_sizes[2] / 5;
    int B = in_sizes[4] / HS;
    int BE = B * NEG;
    const int* src = ei;
    const int* dst = ei + E;

    float* out  = (float*)d_out;
    float* Tout = out;
    float* Dout = out + BE;
    float* Hout = out + 2 * BE;

    k_init_h<<<N, HD>>>(x, node_w, node_b);
    k_init_e<<<E, HD>>>(ea, edgep_w, edgep_b);

    int nb_n = (N + 3) / 4, nb_e = (E + 3) / 4;
    k_eproj<<<NLAYER * nb_e, HD>>>(gat_le, att_ed, E, nb_e);

    for (int l = 0; l < NLAYER; l++) {
        k_attn   <<<nb_n, HD>>>(gat_lin + l * HD * HD, att_src + l * HEADS * CDIM,
                                att_dst + l * HEADS * CDIM, N);
        k_edgeagg<<<E + N, HD>>>(src, dst, l, N, E);
        k_ln     <<<N, HD>>>(gat_b + l * HD, ln_s + l * HD, ln_b + l * HD);
    }

    k_mlp <<<N + E, 64>>>(on_w1, on_b1, on_w2, on_b2, cp_w1, cp_b1, cp_w2, cp_b2, N);
    k_dna <<<1, 1024>>>(x, N, B);
    int tot = N + E + B * HS;
    k_basm<<<(tot + 255) / 256, 256>>>(src, dst, batch, GL, GR, N, E, B);
    k_hwrite<<<(B * HS * HS + 255) / 256, 256>>>(Hout, B);
    k_lu   <<<(BE + 127) / 128, 128>>>(BE);
    k_solve<<<BE * 4, 32>>>(GL, GR, Tout, Dout, BE);
}

// round 16
// speedup vs baseline: 1.0931x; 1.0931x over previous
#include <cuda_runtime.h>
#include <math.h>

#define HD     128
#define HEADS  4
#define CDIM   32
#define NLAYER 4
#define NEG    100
#define HS     128

#define N_MAX  2048
#define E_MAX  4096
#define B_MAX  32
#define BE_MAX (B_MAX * NEG)

// ---------------- scratch (device globals; no allocation allowed) ----------
__device__ float g_h   [N_MAX * HD];
__device__ float g_e   [E_MAX * HD];
__device__ float g_xl  [N_MAX * HD];
__device__ float g_ssrc[N_MAX * HEADS];
__device__ float g_sdst[N_MAX * HEADS];
__device__ float g_ae  [E_MAX * HEADS];
__device__ float g_aesum[HEADS];
__device__ float g_den  [N_MAX * HEADS];
__device__ float g_agg  [N_MAX * HD];
__device__ float g_onsite[N_MAX];
__device__ float g_coup  [E_MAX];
__device__ int   g_dna  [N_MAX];
__device__ int   g_loc  [N_MAX];
// NEGF scratch
__device__ float g_hbd[B_MAX * HS];
__device__ float g_hb1[B_MAX * HS];
__device__ float g_hb2[B_MAX * HS];
__device__ float g_dvb[B_MAX * HS];
__device__ float2 g_lu[BE_MAX * 5 * HS];
__device__ float g_Tacc[BE_MAX];
__device__ float g_Dacc[BE_MAX];
__device__ int   g_cnt [BE_MAX];

// complex mul / fms helpers
#define CMUL(o, a, b) do { \
    (o).x = (a).x * (b).x - (a).y * (b).y; \
    (o).y = (a).x * (b).y + (a).y * (b).x; \
} while (0)
#define CFMS(m, c, r) do { \
    (m).x = fmaf(-(c).x, (r).x, fmaf((c).y, (r).y, (m).x)); \
    (m).y = fmaf(-(c).x, (r).y, fmaf(-(c).y, (r).x, (m).y)); \
} while (0)

// ---------------- GNN kernels ----------------------------------------------
__global__ void k_init_h(const float* __restrict__ x, const float* __restrict__ w,
                         const float* __restrict__ b) {
    int n = blockIdx.x, t = threadIdx.x;
    float acc = b[t];
#pragma unroll
    for (int k = 0; k < 4; k++) acc = fmaf(x[n * 4 + k], w[k * HD + t], acc);
    g_h[n * HD + t] = acc;
    g_agg[n * HD + t] = 0.f;
    if (t < HEADS) g_den[n * HEADS + t] = 0.f;
    if (n == 0 && t < HEADS) g_aesum[t] = 0.f;
}

__global__ void k_init_e(const float* __restrict__ ea, const float* __restrict__ w,
                         const float* __restrict__ b) {
    int n = blockIdx.x, t = threadIdx.x;
    float acc = b[t];
#pragma unroll
    for (int k = 0; k < 5; k++) acc = fmaf(ea[n * 5 + k], w[k * HD + t], acc);
    g_e[n * HD + t] = acc;
}

// fused xl (nodes) + edge-attention projection: 4 rows per block.
// Inner loop stages 16 W values in registers before the FMA block (MLP=16)
// to cover the ~234-cycle L2-hit latency on the weight stream.
__global__ void k_attn(const float* __restrict__ Wn, const float* __restrict__ asrc,
                       const float* __restrict__ adst, const float* __restrict__ We,
                       const float* __restrict__ aedge, int N, int E, int nb_n) {
    __shared__ float rows[4][HD];
    __shared__ float outs[4][HD];
    int t = threadIdx.x;
    bool isnode = (blockIdx.x < nb_n);
    int r0 = (isnode ? blockIdx.x : blockIdx.x - nb_n) * 4;
    int cnt = (isnode ? N : E) - r0; if (cnt > 4) cnt = 4;
    const float* base = isnode ? g_h : g_e;
    const float* W = isnode ? Wn : We;
#pragma unroll
    for (int rr = 0; rr < 4; rr++)
        rows[rr][t] = (rr < cnt) ? base[(size_t)(r0 + rr) * HD + t] : 0.f;
    __syncthreads();
    float a0 = 0.f, a1 = 0.f, a2 = 0.f, a3 = 0.f;
#pragma unroll
    for (int k0 = 0; k0 < HD; k0 += 16) {
        float wv[16];
#pragma unroll
        for (int u = 0; u < 16; u++) wv[u] = W[(k0 + u) * HD + t];
#pragma unroll
        for (int u = 0; u < 16; u++) {
            int k = k0 + u;
            a0 = fmaf(rows[0][k], wv[u], a0);
            a1 = fmaf(rows[1][k], wv[u], a1);
            a2 = fmaf(rows[2][k], wv[u], a2);
            a3 = fmaf(rows[3][k], wv[u], a3);
        }
    }
    outs[0][t] = a0; outs[1][t] = a1; outs[2][t] = a2; outs[3][t] = a3;
    if (isnode) {
        if (0 < cnt) g_xl[(size_t)(r0 + 0) * HD + t] = a0;
        if (1 < cnt) g_xl[(size_t)(r0 + 1) * HD + t] = a1;
        if (2 < cnt) g_xl[(size_t)(r0 + 2) * HD + t] = a2;
        if (3 < cnt) g_xl[(size_t)(r0 + 3) * HD + t] = a3;
    }
    __syncthreads();
    int w = t >> 5, lane = t & 31;
    if (w < cnt) {
        if (isnode) {
#pragma unroll
            for (int h = 0; h < HEADS; h++) {
                float xv = outs[w][h * 32 + lane];
                float vs = xv * asrc[h * 32 + lane];
                float vd = xv * adst[h * 32 + lane];
#pragma unroll
                for (int o = 16; o > 0; o >>= 1) {
                    vs += __shfl_down_sync(0xffffffffu, vs, o);
                    vd += __shfl_down_sync(0xffffffffu, vd, o);
                }
                if (lane == 0) {
                    g_ssrc[(r0 + w) * HEADS + h] = vs;
                    g_sdst[(r0 + w) * HEADS + h] = vd;
                }
            }
        } else {
#pragma unroll
            for (int h = 0; h < HEADS; h++) {
                float v = outs[w][h * 32 + lane] * aedge[h * 32 + lane];
#pragma unroll
                for (int o = 16; o > 0; o >>= 1)
                    v += __shfl_down_sync(0xffffffffu, v, o);
                if (lane == 0) {
                    g_ae[(r0 + w) * HEADS + h] = v;
                    atomicAdd(&g_aesum[h], v);
                }
            }
        }
    }
}

// fused attention-weight + aggregation (softmax shift cancels exactly):
// U[d] += xl[s]*exp(alpha), den[d] += exp(alpha); k_ln divides.
__global__ void k_edgeagg(const int* __restrict__ src, const int* __restrict__ dst,
                          int N, int E) {
    int f = blockIdx.x, t = threadIdx.x;
    int hh = t >> 5, lane = t & 31;
    int s, d; float ae;
    if (f < E) { s = src[f]; d = dst[f]; ae = g_ae[f * HEADS + hh]; }
    else       { s = f - E; d = s;       ae = g_aesum[hh] / (float)E; }
    float a = g_ssrc[s * HEADS + hh] + g_sdst[d * HEADS + hh] + ae;
    a = a > 0.f ? a : 0.2f * a;
    float ex = expf(a);
    atomicAdd(&g_agg[d * HD + t], g_xl[(size_t)s * HD + t] * ex);
    if (lane == 0) atomicAdd(&g_den[d * HEADS + hh], ex);
}

// layernorm(relu(agg/den + bias) + h); zero accumulators for the next layer
__global__ void k_ln(const float* __restrict__ bias, const float* __restrict__ s,
                     const float* __restrict__ bb) {
    __shared__ float red[HD];
    int n = blockIdx.x, t = threadIdx.x;
    float den = g_den[n * HEADS + (t >> 5)];
    float v = g_agg[n * HD + t] / den + bias[t];
    g_agg[n * HD + t] = 0.f;
    __syncthreads();                       // all den reads done before zeroing
    if (t < HEADS) g_den[n * HEADS + t] = 0.f;
    v = v > 0.f ? v : 0.f;
    v += g_h[n * HD + t];
    red[t] = v; __syncthreads();
#pragma unroll
    for (int o = 64; o > 0; o >>= 1) { if (t < o) red[t] += red[t + o]; __syncthreads(); }
    float mu = red[0] / (float)HD;
    __syncthreads();
    float dd = v - mu;
    red[t] = dd * dd; __syncthreads();
#pragma unroll
    for (int o = 64; o > 0; o >>= 1) { if (t < o) red[t] += red[t + o]; __syncthreads(); }
    float var = red[0] / (float)HD;
    g_h[n * HD + t] = dd * rsqrtf(var + 1e-5f) * s[t] + bb[t];
    if (n == 0 && t < HEADS) g_aesum[t] = 0.f;
}

// onsite (nodes) + coupling (edges) MLPs: 128 -> 64 (relu) -> 1.
// Same 16-wide register staging of the weight stream.
__global__ void k_mlp(const float* __restrict__ w1, const float* __restrict__ b1,
                      const float* __restrict__ w2, const float* __restrict__ b2,
                      const float* __restrict__ cw1, const float* __restrict__ cb1,
                      const float* __restrict__ cw2, const float* __restrict__ cb2,
                      int N) {
    __shared__ float in[HD];
    __shared__ float red[64];
    int blk = blockIdx.x, t = threadIdx.x;
    const float *row, *W1, *B1, *W2, *B2;
    if (blk < N) { row = &g_h[(size_t)blk * HD];       W1 = w1;  B1 = b1;  W2 = w2;  B2 = b2;  }
    else         { row = &g_e[(size_t)(blk - N) * HD]; W1 = cw1; B1 = cb1; W2 = cw2; B2 = cb2; }
    in[t] = row[t]; in[t + 64] = row[t + 64];
    __syncthreads();
    float acc = B1[t];
#pragma unroll
    for (int k0 = 0; k0 < HD; k0 += 16) {
        float wv[16];
#pragma unroll
        for (int u = 0; u < 16; u++) wv[u] = W1[(k0 + u) * 64 + t];
#pragma unroll
        for (int u = 0; u < 16; u++) acc = fmaf(in[k0 + u], wv[u], acc);
    }
    acc = acc > 0.f ? acc : 0.f;
    red[t] = acc * W2[t];
    __syncthreads();
#pragma unroll
    for (int o = 32; o > 0; o >>= 1) { if (t < o) red[t] += red[t + o]; __syncthreads(); }
    if (t == 0) {
        float o = red[0] + B2[0];
        if (blk < N) g_onsite[blk] = o; else g_coup[blk - N] = o;
    }
}

// dna mask + local index: warp-per-graph ballot scan; zero band arrays
__global__ void k_dna(const float* __restrict__ x, int N, int B) {
    int t = threadIdx.x;
    for (int i = t; i < B * HS; i += blockDim.x) {
        g_hbd[i] = 0.f; g_hb1[i] = 0.f; g_hb2[i] = 0.f;
    }
    int warp = t >> 5, lane = t & 31;
    int npg = N / B;
    if (warp < B) {
        int base = warp * npg;
        int off = 0;
        for (int c = 0; c < npg; c += 32) {
            int li = c + lane;
            int mi = 0;
            if (li < npg) {
                int n = base + li;
                float a = x[n * 4], b = x[n * 4 + 1], cc = x[n * 4 + 2], d = x[n * 4 + 3];
                mi = (a != 0.f || b != 0.f || cc != 0.f || d != 0.f) ? 1 : 0;
                g_dna[n] = mi;
            }
            unsigned bits = __ballot_sync(0xffffffffu, mi);
            if (li < npg) g_loc[base + li] = off + __popc(bits & ((1u << lane) - 1u));
            off += __popc(bits);
        }
    }
}

// assemble bands: onsite->diag, coup->band1/band2, dvb from GL/GR
__global__ void k_basm(const int* __restrict__ src, const int* __restrict__ dst,
                       const int* __restrict__ batch,
                       const float* __restrict__ GL, const float* __restrict__ GR,
                       int N, int E, int B) {
    int idx = blockIdx.x * blockDim.x + threadIdx.x;
    if (idx < N) {
        if (g_dna[idx])
            atomicAdd(&g_hbd[batch[idx] * HS + g_loc[idx]], g_onsite[idx]);
    } else if (idx < N + E) {
        int e = idx - N;
        int s = src[e], d = dst[e];
        if (g_dna[s] && g_dna[d]) {
            int b = batch[s], u = g_loc[s], v = g_loc[d];
            int lo = u < v ? u : v;
            int bd = u < v ? v - u : u - v;
            float cv = g_coup[e];
            if (bd == 1)      atomicAdd(&g_hb1[b * HS + lo], cv);
            else if (bd == 2) atomicAdd(&g_hb2[b * HS + lo], cv);
        }
    } else if (idx < N + E + B * HS) {
        int i = idx - N - E;
        g_dvb[i] = 0.5f * (GL[i] + GR[i]) + 1e-12f;
    }
}

// write dense H (output) from bands
__global__ void k_hwrite(float* __restrict__ H, int B) {
    int idx = blockIdx.x * blockDim.x + threadIdx.x;
    if (idx >= B * HS * HS) return;
    int b = idx / (HS * HS);
    int r = (idx % (HS * HS)) / HS, c = idx % HS;
    float v;
    int lo = r < c ? r : c;
    int bd = r < c ? c - r : r - c;
    if (bd == 0)      v = g_hbd[b * HS + r] + 1e-6f;
    else if (bd == 1) v = g_hb1[b * HS + lo];
    else if (bd == 2) v = g_hb2[b * HS + lo];
    else              v = 0.f;
    H[idx] = v;
}

// ---------------- NEGF: banded (pentadiagonal) solver ----------------------
__global__ void k_lu(int BE) {
    int be = blockIdx.x * blockDim.x + threadIdx.x;
    if (be >= BE) return;
    int b = be / NEG, e = be % NEG;
    float Eg = (float)(-3.0 + 6.0 * (double)e / 99.0);
    const float* hd = g_hbd + b * HS;
    const float* h1 = g_hb1 + b * HS;
    const float* h2 = g_hb2 + b * HS;
    const float* dv = g_dvb + b * HS;
    float2* out = g_lu + (size_t)be * 5 * HS;
    g_Tacc[be] = 0.f; g_Dacc[be] = 0.f; g_cnt[be] = 0;

    float2 e1 = {0.f, 0.f}, e2 = {0.f, 0.f};
    float2 f1 = {0.f, 0.f}, f2 = {0.f, 0.f};
    float2 di1 = {0.f, 0.f}, di2 = {0.f, 0.f};
    for (int i = 0; i < HS; i++) {
        float2 Mi = make_float2(Eg - (hd[i] + 1e-6f), dv[i]);
        float m1 = (i >= 1) ? -h1[i - 1] : 0.f;
        float m2 = (i >= 2) ? -h2[i - 2] : 0.f;
        float2 bi = make_float2(m2 * di2.x, m2 * di2.y);
        float2 tt = make_float2(m1, 0.f);
        CFMS(tt, bi, e2);
        float2 ai; CMUL(ai, tt, di1);
        float2 d = Mi;
        CFMS(d, bi, f2);
        CFMS(d, ai, e1);
        float2 ei = make_float2(0.f, 0.f);
        if (i < HS - 1) { ei = make_float2(-h1[i], 0.f); CFMS(ei, ai, f1); }
        float2 fi = make_float2((i < HS - 2) ? -h2[i] : 0.f, 0.f);
        float inv = 1.f / fmaf(d.x, d.x, d.y * d.y);
        float2 dinv = make_float2(d.x * inv, -d.y * inv);
        out[0 * HS + i] = ai;
        out[1 * HS + i] = bi;
        out[2 * HS + i] = ei;
        out[3 * HS + i] = fi;
        out[4 * HS + i] = dinv;
        e2 = e1; e1 = ei; f2 = f1; f1 = fi; di2 = di1; di1 = dinv;
    }
}

// column solves: one warp-CTA per (b,e, quarter); lane = column j.
__global__ void __launch_bounds__(32) k_solve(
    const float* __restrict__ GL, const float* __restrict__ GR,
    float* __restrict__ Tout, float* __restrict__ Dout, int BE) {
    __shared__ float2 ys[HS * 32];
    __shared__ float2 sa[HS], sb[HS], se[HS], sf[HS], sdi[HS];
    __shared__ float  sgl[HS], sgr[HS];
    int blk = blockIdx.x;
    int be = blk >> 2, q = blk & 3;
    int b = be / NEG;
    int lane = threadIdx.x;
    const float2* lu = g_lu + (size_t)be * 5 * HS;
#pragma unroll
    for (int k = 0; k < 4; k++) {
        int i = lane + k * 32;
        sa[i]  = lu[0 * HS + i];
        sb[i]  = lu[1 * HS + i];
        se[i]  = lu[2 * HS + i];
        sf[i]  = lu[3 * HS + i];
        sdi[i] = lu[4 * HS + i];
        sgl[i] = GL[b * HS + i];
        sgr[i] = GR[b * HS + i];
    }
    __syncwarp();

    int j = q * 32 + lane;
    int i0 = q * 32;
    float2 y1 = {0.f, 0.f}, y2 = {0.f, 0.f};
    for (int i = i0; i < HS; i++) {
        float2 y = make_float2((i == j) ? 1.f : 0.f, 0.f);
        CFMS(y, sa[i], y1);
        CFMS(y, sb[i], y2);
        ys[i * 32 + lane] = y;
        y2 = y1; y1 = y;
    }
    float2 x1 = {0.f, 0.f}, x2 = {0.f, 0.f};
    float tp = 0.f, dj = 0.f;
    for (int i = HS - 1; i >= 0; i--) {
        float2 t = (i >= i0) ? ys[i * 32 + lane] : make_float2(0.f, 0.f);
        CFMS(t, se[i], x1);
        CFMS(t, sf[i], x2);
        float2 x; CMUL(x, t, sdi[i]);
        tp = fmaf(sgl[i], fmaf(x.x, x.x, x.y * x.y), tp);
        if (i == j) dj = x.y;
        x2 = x1; x1 = x;
    }
    tp *= sgr[j];
#pragma unroll
    for (int o = 16; o > 0; o >>= 1) {
        tp += __shfl_down_sync(0xffffffffu, tp, o);
        dj += __shfl_down_sync(0xffffffffu, dj, o);
    }
    if (lane == 0) {
        atomicAdd(&g_Tacc[be], tp);
        atomicAdd(&g_Dacc[be], dj);
        __threadfence();
        int old = atomicAdd(&g_cnt[be], 1);
        if (old == 3) {
            __threadfence();
            Tout[be] = log10f(fmaxf(g_Tacc[be], 1e-16f));
            Dout[be] = log10f(fmaxf(-g_Dacc[be] / 3.14159265358979323846f, 1e-16f));
        }
    }
}

// ---------------- launch ----------------------------------------------------
extern "C" void kernel_launch(void* const* d_in, const int* in_sizes, int n_in,
                              void* d_out, int out_size) {
    const float* x      = (const float*)d_in[0];
    const int*   ei     = (const int*)  d_in[1];
    const float* ea     = (const float*)d_in[2];
    const int*   batch  = (const int*)  d_in[3];
    const float* GL     = (const float*)d_in[4];
    const float* GR     = (const float*)d_in[5];
    const float* node_w = (const float*)d_in[6];
    const float* node_b = (const float*)d_in[7];
    const float* edgep_w= (const float*)d_in[8];
    const float* edgep_b= (const float*)d_in[9];
    const float* gat_lin= (const float*)d_in[10];
    const float* att_src= (const float*)d_in[11];
    const float* att_dst= (const float*)d_in[12];
    const float* gat_le = (const float*)d_in[13];
    const float* att_ed = (const float*)d_in[14];
    const float* gat_b  = (const float*)d_in[15];
    const float* ln_s   = (const float*)d_in[16];
    const float* ln_b   = (const float*)d_in[17];
    const float* on_w1  = (const float*)d_in[18];
    const float* on_b1  = (const float*)d_in[19];
    const float* on_w2  = (const float*)d_in[20];
    const float* on_b2  = (const float*)d_in[21];
    const float* cp_w1  = (const float*)d_in[22];
    const float* cp_b1  = (const float*)d_in[23];
    const float* cp_w2  = (const float*)d_in[24];
    const float* cp_b2  = (const float*)d_in[25];

    int N = in_sizes[0] / 4;
    int E = in_sizes[2] / 5;
    int B = in_sizes[4] / HS;
    int BE = B * NEG;
    const int* src = ei;
    const int* dst = ei + E;

    float* out  = (float*)d_out;
    float* Tout = out;
    float* Dout = out + BE;
    float* Hout = out + 2 * BE;

    k_init_h<<<N, HD>>>(x, node_w, node_b);
    k_init_e<<<E, HD>>>(ea, edgep_w, edgep_b);

    int nb_n = (N + 3) / 4, nb_e = (E + 3) / 4;
    for (int l = 0; l < NLAYER; l++) {
        k_attn   <<<nb_n + nb_e, HD>>>(gat_lin + l * HD * HD, att_src + l * HEADS * CDIM,
                                       att_dst + l * HEADS * CDIM, gat_le + l * HD * HD,
                                       att_ed + l * HEADS * CDIM, N, E, nb_n);
        k_edgeagg<<<E + N, HD>>>(src, dst, N, E);
        k_ln     <<<N, HD>>>(gat_b + l * HD, ln_s + l * HD, ln_b + l * HD);
    }

    k_mlp <<<N + E, 64>>>(on_w1, on_b1, on_w2, on_b2, cp_w1, cp_b1, cp_w2, cp_b2, N);
    k_dna <<<1, 1024>>>(x, N, B);
    int tot = N + E + B * HS;
    k_basm<<<(tot + 255) / 256, 256>>>(src, dst, batch, GL, GR, N, E, B);
    k_hwrite<<<(B * HS * HS + 255) / 256, 256>>>(Hout, B);
    k_lu   <<<(BE + 127) / 128, 128>>>(BE);
    k_solve<<<BE * 4, 32>>>(GL, GR, Tout, Dout, BE);
}

// round 17
// speedup vs baseline: 1.0945x; 1.0013x over previous
#include <cuda_runtime.h>
#include <math.h>

#define HD     128
#define HEADS  4
#define CDIM   32
#define NLAYER 4
#define NEG    100
#define HS     128

#define N_MAX  2048
#define E_MAX  4096
#define B_MAX  32
#define BE_MAX (B_MAX * NEG)

// ---------------- scratch (device globals; no allocation allowed) ----------
__device__ float g_h   [N_MAX * HD];
__device__ float g_e   [E_MAX * HD];
__device__ float g_xl  [N_MAX * HD];
__device__ float g_ssrc[N_MAX * HEADS];
__device__ float g_sdst[N_MAX * HEADS];
__device__ float g_ae  [E_MAX * HEADS];
__device__ float g_aesum2[NLAYER * HEADS];
__device__ float g_den  [N_MAX * HEADS];
__device__ float g_agg  [N_MAX * HD];
__device__ float g_onsite[N_MAX];
__device__ float g_coup  [E_MAX];
__device__ int   g_dna  [N_MAX];
__device__ int   g_loc  [N_MAX];
// NEGF scratch
__device__ float g_hbd[B_MAX * HS];
__device__ float g_hb1[B_MAX * HS];
__device__ float g_hb2[B_MAX * HS];
__device__ float g_dvb[B_MAX * HS];
__device__ float2 g_lu[BE_MAX * 5 * HS];
__device__ float g_Tacc[BE_MAX];
__device__ float g_Dacc[BE_MAX];
__device__ int   g_cnt [BE_MAX];

// complex mul / fms helpers
#define CMUL(o, a, b) do { \
    (o).x = (a).x * (b).x - (a).y * (b).y; \
    (o).y = (a).x * (b).y + (a).y * (b).x; \
} while (0)
#define CFMS(m, c, r) do { \
    (m).x = fmaf(-(c).x, (r).x, fmaf((c).y, (r).y, (m).x)); \
    (m).y = fmaf(-(c).x, (r).y, fmaf(-(c).y, (r).x, (m).y)); \
} while (0)

// ---------------- GNN kernels ----------------------------------------------
__global__ void k_init_h(const float* __restrict__ x, const float* __restrict__ w,
                         const float* __restrict__ b) {
    int n = blockIdx.x, t = threadIdx.x;
    float acc = b[t];
#pragma unroll
    for (int k = 0; k < 4; k++) acc = fmaf(x[n * 4 + k], w[k * HD + t], acc);
    g_h[n * HD + t] = acc;
    g_agg[n * HD + t] = 0.f;
    if (t < HEADS) g_den[n * HEADS + t] = 0.f;
    if (n == 0 && t < NLAYER * HEADS) g_aesum2[t] = 0.f;
}

__global__ void k_init_e(const float* __restrict__ ea, const float* __restrict__ w,
                         const float* __restrict__ b) {
    int n = blockIdx.x, t = threadIdx.x;
    float acc = b[t];
#pragma unroll
    for (int k = 0; k < 5; k++) acc = fmaf(ea[n * 5 + k], w[k * HD + t], acc);
    g_e[n * HD + t] = acc;
}

// fused [LN of previous layer, node rows only] + projection + attention dots.
// 4 rows per block; node blocks then edge blocks. first=1 skips the LN.
// aesum accumulated into per-layer slot (device-side indexing).
__global__ void k_lnattn(const float* __restrict__ Wn, const float* __restrict__ asrc,
                         const float* __restrict__ adst, const float* __restrict__ We,
                         const float* __restrict__ aedge,
                         const float* __restrict__ bias, const float* __restrict__ lns,
                         const float* __restrict__ lnb,
                         int l, int N, int E, int nb_n, int first) {
    __shared__ float rows[4][HD];
    __shared__ float outs[4][HD];
    __shared__ float redh[4], redv[4];
    int t = threadIdx.x;
    int w = t >> 5, lane = t & 31;
    bool isnode = (blockIdx.x < nb_n);
    int r0 = (isnode ? blockIdx.x : blockIdx.x - nb_n) * 4;
    int cnt = (isnode ? N : E) - r0; if (cnt > 4) cnt = 4;
    const float* W = isnode ? Wn : We;

    if (!isnode) {
#pragma unroll
        for (int rr = 0; rr < 4; rr++)
            rows[rr][t] = (rr < cnt) ? g_e[(size_t)(r0 + rr) * HD + t] : 0.f;
        __syncthreads();
    } else if (first) {
#pragma unroll
        for (int rr = 0; rr < 4; rr++)
            rows[rr][t] = (rr < cnt) ? g_h[(size_t)(r0 + rr) * HD + t] : 0.f;
        __syncthreads();
    } else {
        // LN of previous layer for this block's 4 node rows
#pragma unroll
        for (int rr = 0; rr < 4; rr++) {
            int n = r0 + rr;
            bool valid = (rr < cnt);
            float v = 0.f;
            if (valid) {
                float den = g_den[n * HEADS + w];
                v = g_agg[n * HD + t] / den + bias[t];
                g_agg[n * HD + t] = 0.f;
            }
            __syncthreads();                        // den reads before zeroing
            if (valid && t < HEADS) g_den[n * HEADS + t] = 0.f;
            if (valid) {
                v = v > 0.f ? v : 0.f;
                v += g_h[n * HD + t];
            }
            float s1 = v;
#pragma unroll
            for (int o = 16; o > 0; o >>= 1) s1 += __shfl_down_sync(0xffffffffu, s1, o);
            if (lane == 0) redh[w] = s1;
            __syncthreads();
            float mu = (redh[0] + redh[1] + redh[2] + redh[3]) * (1.f / HD);
            float dd = valid ? v - mu : 0.f;
            float s2 = dd * dd;
#pragma unroll
            for (int o = 16; o > 0; o >>= 1) s2 += __shfl_down_sync(0xffffffffu, s2, o);
            if (lane == 0) redv[w] = s2;
            __syncthreads();
            float var = (redv[0] + redv[1] + redv[2] + redv[3]) * (1.f / HD);
            float hv = dd * rsqrtf(var + 1e-5f) * lns[t] + lnb[t];
            if (valid) g_h[(size_t)n * HD + t] = hv;
            rows[rr][t] = valid ? hv : 0.f;
            __syncthreads();
        }
    }

    // projection (16-wide register-staged weight stream)
    float a0 = 0.f, a1 = 0.f, a2 = 0.f, a3 = 0.f;
#pragma unroll
    for (int k0 = 0; k0 < HD; k0 += 16) {
        float wv[16];
#pragma unroll
        for (int u = 0; u < 16; u++) wv[u] = W[(k0 + u) * HD + t];
#pragma unroll
        for (int u = 0; u < 16; u++) {
            int k = k0 + u;
            a0 = fmaf(rows[0][k], wv[u], a0);
            a1 = fmaf(rows[1][k], wv[u], a1);
            a2 = fmaf(rows[2][k], wv[u], a2);
            a3 = fmaf(rows[3][k], wv[u], a3);
        }
    }
    outs[0][t] = a0; outs[1][t] = a1; outs[2][t] = a2; outs[3][t] = a3;
    if (isnode) {
        if (0 < cnt) g_xl[(size_t)(r0 + 0) * HD + t] = a0;
        if (1 < cnt) g_xl[(size_t)(r0 + 1) * HD + t] = a1;
        if (2 < cnt) g_xl[(size_t)(r0 + 2) * HD + t] = a2;
        if (3 < cnt) g_xl[(size_t)(r0 + 3) * HD + t] = a3;
    }
    __syncthreads();
    if (w < cnt) {
        if (isnode) {
#pragma unroll
            for (int h = 0; h < HEADS; h++) {
                float xv = outs[w][h * 32 + lane];
                float vs = xv * asrc[h * 32 + lane];
                float vd = xv * adst[h * 32 + lane];
#pragma unroll
                for (int o = 16; o > 0; o >>= 1) {
                    vs += __shfl_down_sync(0xffffffffu, vs, o);
                    vd += __shfl_down_sync(0xffffffffu, vd, o);
                }
                if (lane == 0) {
                    g_ssrc[(r0 + w) * HEADS + h] = vs;
                    g_sdst[(r0 + w) * HEADS + h] = vd;
                }
            }
        } else {
#pragma unroll
            for (int h = 0; h < HEADS; h++) {
                float v = outs[w][h * 32 + lane] * aedge[h * 32 + lane];
#pragma unroll
                for (int o = 16; o > 0; o >>= 1)
                    v += __shfl_down_sync(0xffffffffu, v, o);
                if (lane == 0) {
                    g_ae[(r0 + w) * HEADS + h] = v;
                    atomicAdd(&g_aesum2[l * HEADS + h], v);
                }
            }
        }
    }
}

// fused attention-weight + aggregation (softmax shift cancels exactly);
// per-layer aesum slot read device-side.
__global__ void k_edgeagg(const int* __restrict__ src, const int* __restrict__ dst,
                          int l, int N, int E) {
    int f = blockIdx.x, t = threadIdx.x;
    int hh = t >> 5, lane = t & 31;
    int s, d; float ae;
    if (f < E) { s = src[f]; d = dst[f]; ae = g_ae[f * HEADS + hh]; }
    else       { s = f - E; d = s;       ae = g_aesum2[l * HEADS + hh] / (float)E; }
    float a = g_ssrc[s * HEADS + hh] + g_sdst[d * HEADS + hh] + ae;
    a = a > 0.f ? a : 0.2f * a;
    float ex = expf(a);
    atomicAdd(&g_agg[d * HD + t], g_xl[(size_t)s * HD + t] * ex);
    if (lane == 0) atomicAdd(&g_den[d * HEADS + hh], ex);
}

// final layernorm (last layer only)
__global__ void k_ln(const float* __restrict__ bias, const float* __restrict__ s,
                     const float* __restrict__ bb) {
    __shared__ float red[HD];
    int n = blockIdx.x, t = threadIdx.x;
    float den = g_den[n * HEADS + (t >> 5)];
    float v = g_agg[n * HD + t] / den + bias[t];
    v = v > 0.f ? v : 0.f;
    v += g_h[n * HD + t];
    red[t] = v; __syncthreads();
#pragma unroll
    for (int o = 64; o > 0; o >>= 1) { if (t < o) red[t] += red[t + o]; __syncthreads(); }
    float mu = red[0] / (float)HD;
    __syncthreads();
    float dd = v - mu;
    red[t] = dd * dd; __syncthreads();
#pragma unroll
    for (int o = 64; o > 0; o >>= 1) { if (t < o) red[t] += red[t + o]; __syncthreads(); }
    float var = red[0] / (float)HD;
    g_h[n * HD + t] = dd * rsqrtf(var + 1e-5f) * s[t] + bb[t];
}

// onsite/coupling MLPs (blocks 0..N+E-1) + dna ballot scan (last block).
__global__ void k_mlp(const float* __restrict__ w1, const float* __restrict__ b1,
                      const float* __restrict__ w2, const float* __restrict__ b2,
                      const float* __restrict__ cw1, const float* __restrict__ cb1,
                      const float* __restrict__ cw2, const float* __restrict__ cb2,
                      const float* __restrict__ x, int N, int E, int B) {
    __shared__ float in[HD];
    __shared__ float red[64];
    int blk = blockIdx.x, t = threadIdx.x;
    if (blk == N + E) {
        // dna block: zero bands + warp-per-graph ballot scan (2 warps loop)
        for (int i = t; i < B * HS; i += 64) {
            g_hbd[i] = 0.f; g_hb1[i] = 0.f; g_hb2[i] = 0.f;
        }
        int warp = t >> 5, lane = t & 31;
        int npg = N / B;
        for (int g = warp; g < B; g += 2) {
            int base = g * npg;
            int off = 0;
            for (int c = 0; c < npg; c += 32) {
                int li = c + lane;
                int mi = 0;
                if (li < npg) {
                    int n = base + li;
                    float a = x[n * 4], b = x[n * 4 + 1];
                    float cc = x[n * 4 + 2], d = x[n * 4 + 3];
                    mi = (a != 0.f || b != 0.f || cc != 0.f || d != 0.f) ? 1 : 0;
                    g_dna[n] = mi;
                }
                unsigned bits = __ballot_sync(0xffffffffu, mi);
                if (li < npg) g_loc[base + li] = off + __popc(bits & ((1u << lane) - 1u));
                off += __popc(bits);
            }
        }
        return;
    }
    const float *row, *W1, *B1, *W2, *B2;
    if (blk < N) { row = &g_h[(size_t)blk * HD];       W1 = w1;  B1 = b1;  W2 = w2;  B2 = b2;  }
    else         { row = &g_e[(size_t)(blk - N) * HD]; W1 = cw1; B1 = cb1; W2 = cw2; B2 = cb2; }
    in[t] = row[t]; in[t + 64] = row[t + 64];
    __syncthreads();
    float acc = B1[t];
#pragma unroll
    for (int k0 = 0; k0 < HD; k0 += 16) {
        float wv[16];
#pragma unroll
        for (int u = 0; u < 16; u++) wv[u] = W1[(k0 + u) * 64 + t];
#pragma unroll
        for (int u = 0; u < 16; u++) acc = fmaf(in[k0 + u], wv[u], acc);
    }
    acc = acc > 0.f ? acc : 0.f;
    red[t] = acc * W2[t];
    __syncthreads();
#pragma unroll
    for (int o = 32; o > 0; o >>= 1) { if (t < o) red[t] += red[t + o]; __syncthreads(); }
    if (t == 0) {
        float o = red[0] + B2[0];
        if (blk < N) g_onsite[blk] = o; else g_coup[blk - N] = o;
    }
}

// assemble bands: onsite->diag, coup->band1/band2, dvb from GL/GR
__global__ void k_basm(const int* __restrict__ src, const int* __restrict__ dst,
                       const int* __restrict__ batch,
                       const float* __restrict__ GL, const float* __restrict__ GR,
                       int N, int E, int B) {
    int idx = blockIdx.x * blockDim.x + threadIdx.x;
    if (idx < N) {
        if (g_dna[idx])
            atomicAdd(&g_hbd[batch[idx] * HS + g_loc[idx]], g_onsite[idx]);
    } else if (idx < N + E) {
        int e = idx - N;
        int s = src[e], d = dst[e];
        if (g_dna[s] && g_dna[d]) {
            int b = batch[s], u = g_loc[s], v = g_loc[d];
            int lo = u < v ? u : v;
            int bd = u < v ? v - u : u - v;
            float cv = g_coup[e];
            if (bd == 1)      atomicAdd(&g_hb1[b * HS + lo], cv);
            else if (bd == 2) atomicAdd(&g_hb2[b * HS + lo], cv);
        }
    } else if (idx < N + E + B * HS) {
        int i = idx - N - E;
        g_dvb[i] = 0.5f * (GL[i] + GR[i]) + 1e-12f;
    }
}

// write dense H (output) from bands
__global__ void k_hwrite(float* __restrict__ H, int B) {
    int idx = blockIdx.x * blockDim.x + threadIdx.x;
    if (idx >= B * HS * HS) return;
    int b = idx / (HS * HS);
    int r = (idx % (HS * HS)) / HS, c = idx % HS;
    float v;
    int lo = r < c ? r : c;
    int bd = r < c ? c - r : r - c;
    if (bd == 0)      v = g_hbd[b * HS + r] + 1e-6f;
    else if (bd == 1) v = g_hb1[b * HS + lo];
    else if (bd == 2) v = g_hb2[b * HS + lo];
    else              v = 0.f;
    H[idx] = v;
}

// ---------------- NEGF: banded (pentadiagonal) solver ----------------------
__global__ void k_lu(int BE) {
    int be = blockIdx.x * blockDim.x + threadIdx.x;
    if (be >= BE) return;
    int b = be / NEG, e = be % NEG;
    float Eg = (float)(-3.0 + 6.0 * (double)e / 99.0);
    const float* hd = g_hbd + b * HS;
    const float* h1 = g_hb1 + b * HS;
    const float* h2 = g_hb2 + b * HS;
    const float* dv = g_dvb + b * HS;
    float2* out = g_lu + (size_t)be * 5 * HS;
    g_Tacc[be] = 0.f; g_Dacc[be] = 0.f; g_cnt[be] = 0;

    float2 e1 = {0.f, 0.f}, e2 = {0.f, 0.f};
    float2 f1 = {0.f, 0.f}, f2 = {0.f, 0.f};
    float2 di1 = {0.f, 0.f}, di2 = {0.f, 0.f};
    for (int i = 0; i < HS; i++) {
        float2 Mi = make_float2(Eg - (hd[i] + 1e-6f), dv[i]);
        float m1 = (i >= 1) ? -h1[i - 1] : 0.f;
        float m2 = (i >= 2) ? -h2[i - 2] : 0.f;
        float2 bi = make_float2(m2 * di2.x, m2 * di2.y);
        float2 tt = make_float2(m1, 0.f);
        CFMS(tt, bi, e2);
        float2 ai; CMUL(ai, tt, di1);
        float2 d = Mi;
        CFMS(d, bi, f2);
        CFMS(d, ai, e1);
        float2 ei = make_float2(0.f, 0.f);
        if (i < HS - 1) { ei = make_float2(-h1[i], 0.f); CFMS(ei, ai, f1); }
        float2 fi = make_float2((i < HS - 2) ? -h2[i] : 0.f, 0.f);
        float inv = 1.f / fmaf(d.x, d.x, d.y * d.y);
        float2 dinv = make_float2(d.x * inv, -d.y * inv);
        out[0 * HS + i] = ai;
        out[1 * HS + i] = bi;
        out[2 * HS + i] = ei;
        out[3 * HS + i] = fi;
        out[4 * HS + i] = dinv;
        e2 = e1; e1 = ei; f2 = f1; f1 = fi; di2 = di1; di1 = dinv;
    }
}

// column solves: one warp-CTA per (b,e, quarter); lane = column j.
__global__ void __launch_bounds__(32) k_solve(
    const float* __restrict__ GL, const float* __restrict__ GR,
    float* __restrict__ Tout, float* __restrict__ Dout, int BE) {
    __shared__ float2 ys[HS * 32];
    __shared__ float2 sa[HS], sb[HS], se[HS], sf[HS], sdi[HS];
    __shared__ float  sgl[HS], sgr[HS];
    int blk = blockIdx.x;
    int be = blk >> 2, q = blk & 3;
    int b = be / NEG;
    int lane = threadIdx.x;
    const float2* lu = g_lu + (size_t)be * 5 * HS;
#pragma unroll
    for (int k = 0; k < 4; k++) {
        int i = lane + k * 32;
        sa[i]  = lu[0 * HS + i];
        sb[i]  = lu[1 * HS + i];
        se[i]  = lu[2 * HS + i];
        sf[i]  = lu[3 * HS + i];
        sdi[i] = lu[4 * HS + i];
        sgl[i] = GL[b * HS + i];
        sgr[i] = GR[b * HS + i];
    }
    __syncwarp();

    int j = q * 32 + lane;
    int i0 = q * 32;
    float2 y1 = {0.f, 0.f}, y2 = {0.f, 0.f};
    for (int i = i0; i < HS; i++) {
        float2 y = make_float2((i == j) ? 1.f : 0.f, 0.f);
        CFMS(y, sa[i], y1);
        CFMS(y, sb[i], y2);
        ys[i * 32 + lane] = y;
        y2 = y1; y1 = y;
    }
    float2 x1 = {0.f, 0.f}, x2 = {0.f, 0.f};
    float tp = 0.f, dj = 0.f;
    for (int i = HS - 1; i >= 0; i--) {
        float2 t = (i >= i0) ? ys[i * 32 + lane] : make_float2(0.f, 0.f);
        CFMS(t, se[i], x1);
        CFMS(t, sf[i], x2);
        float2 x; CMUL(x, t, sdi[i]);
        tp = fmaf(sgl[i], fmaf(x.x, x.x, x.y * x.y), tp);
        if (i == j) dj = x.y;
        x2 = x1; x1 = x;
    }
    tp *= sgr[j];
#pragma unroll
    for (int o = 16; o > 0; o >>= 1) {
        tp += __shfl_down_sync(0xffffffffu, tp, o);
        dj += __shfl_down_sync(0xffffffffu, dj, o);
    }
    if (lane == 0) {
        atomicAdd(&g_Tacc[be], tp);
        atomicAdd(&g_Dacc[be], dj);
        __threadfence();
        int old = atomicAdd(&g_cnt[be], 1);
        if (old == 3) {
            __threadfence();
            Tout[be] = log10f(fmaxf(g_Tacc[be], 1e-16f));
            Dout[be] = log10f(fmaxf(-g_Dacc[be] / 3.14159265358979323846f, 1e-16f));
        }
    }
}

// ---------------- launch ----------------------------------------------------
extern "C" void kernel_launch(void* const* d_in, const int* in_sizes, int n_in,
                              void* d_out, int out_size) {
    const float* x      = (const float*)d_in[0];
    const int*   ei     = (const int*)  d_in[1];
    const float* ea     = (const float*)d_in[2];
    const int*   batch  = (const int*)  d_in[3];
    const float* GL     = (const float*)d_in[4];
    const float* GR     = (const float*)d_in[5];
    const float* node_w = (const float*)d_in[6];
    const float* node_b = (const float*)d_in[7];
    const float* edgep_w= (const float*)d_in[8];
    const float* edgep_b= (const float*)d_in[9];
    const float* gat_lin= (const float*)d_in[10];
    const float* att_src= (const float*)d_in[11];
    const float* att_dst= (const float*)d_in[12];
    const float* gat_le = (const float*)d_in[13];
    const float* att_ed = (const float*)d_in[14];
    const float* gat_b  = (const float*)d_in[15];
    const float* ln_s   = (const float*)d_in[16];
    const float* ln_b   = (const float*)d_in[17];
    const float* on_w1  = (const float*)d_in[18];
    const float* on_b1  = (const float*)d_in[19];
    const float* on_w2  = (const float*)d_in[20];
    const float* on_b2  = (const float*)d_in[21];
    const float* cp_w1  = (const float*)d_in[22];
    const float* cp_b1  = (const float*)d_in[23];
    const float* cp_w2  = (const float*)d_in[24];
    const float* cp_b2  = (const float*)d_in[25];

    int N = in_sizes[0] / 4;
    int E = in_sizes[2] / 5;
    int B = in_sizes[4] / HS;
    int BE = B * NEG;
    const int* src = ei;
    const int* dst = ei + E;

    float* out  = (float*)d_out;
    float* Tout = out;
    float* Dout = out + BE;
    float* Hout = out + 2 * BE;

    k_init_h<<<N, HD>>>(x, node_w, node_b);
    k_init_e<<<E, HD>>>(ea, edgep_w, edgep_b);

    int nb_n = (N + 3) / 4, nb_e = (E + 3) / 4;
    for (int l = 0; l < NLAYER; l++) {
        const float* bias = (l > 0) ? gat_b + (l - 1) * HD : gat_b;
        const float* lns  = (l > 0) ? ln_s + (l - 1) * HD : ln_s;
        const float* lnb  = (l > 0) ? ln_b + (l - 1) * HD : ln_b;
        k_lnattn <<<nb_n + nb_e, HD>>>(gat_lin + l * HD * HD,
                                       att_src + l * HEADS * CDIM,
                                       att_dst + l * HEADS * CDIM,
                                       gat_le + l * HD * HD,
                                       att_ed + l * HEADS * CDIM,
                                       bias, lns, lnb, l, N, E, nb_n,
                                       l == 0 ? 1 : 0);
        k_edgeagg<<<E + N, HD>>>(src, dst, l, N, E);
    }
    k_ln<<<N, HD>>>(gat_b + (NLAYER - 1) * HD, ln_s + (NLAYER - 1) * HD,
                    ln_b + (NLAYER - 1) * HD);

    k_mlp <<<N + E + 1, 64>>>(on_w1, on_b1, on_w2, on_b2,
                              cp_w1, cp_b1, cp_w2, cp_b2, x, N, E, B);
    int tot = N + E + B * HS;
    k_basm<<<(tot + 255) / 256, 256>>>(src, dst, batch, GL, GR, N, E, B);
    k_hwrite<<<(B * HS * HS + 255) / 256, 256>>>(Hout, B);
    k_lu   <<<(BE + 127) / 128, 128>>>(BE);
    k_solve<<<BE * 4, 32>>>(GL, GR, Tout, Dout, BE);
}